// round 1
// baseline (speedup 1.0000x reference)
#include <cuda_runtime.h>
#include <cuda_bf16.h>
#include <math.h>

// Problem constants
#define Bv 32
#define Cv 512
#define Hv 32
#define Wv 32
#define NHv 16
#define WSv 4
#define HDv 32
#define Nv 16
#define Tv 32768              // B*H*W tokens
#define C3v 1536
#define MLPHv 2048
#define EPSv 1e-5f
#define QSCALE 0.1767766952966369f  // 1/sqrt(32)

// ---------------- scratch (device globals; no allocation allowed) ----------
__device__ float g_xh  [Tv * Cv];     // permuted input (window order), residual 1
__device__ float g_xn  [Tv * Cv];     // LN1 output
__device__ float g_qkv [Tv * C3v];    // qkv projection
__device__ float g_att [Tv * Cv];     // attention output (pre-proj)
__device__ float g_xh2 [Tv * Cv];     // after proj + residual
__device__ float g_h2  [Tv * Cv];     // LN2 output
__device__ float g_hid [Tv * MLPHv];  // mlp hidden
__device__ float g_xfin[Tv * Cv];     // final (window order)

// ---------------- K1a: [B,C,H,W] -> window-ordered [T,C] -------------------
__global__ void permute_in_kernel(const float* __restrict__ x, float* __restrict__ xh) {
    __shared__ float tile[32][33];
    int b  = blockIdx.z;
    int hw0 = blockIdx.x * 32;
    int c0  = blockIdx.y * 32;
    int tx = threadIdx.x, ty = threadIdx.y;
    #pragma unroll
    for (int r = 0; r < 32; r += 8) {
        int c = c0 + ty + r;
        tile[ty + r][tx] = x[(((size_t)(b * Cv + c)) << 10) + hw0 + tx];
    }
    __syncthreads();
    #pragma unroll
    for (int r = 0; r < 32; r += 8) {
        int hw = hw0 + ty + r;
        int h = hw >> 5, w = hw & 31;
        int tokloc = (((h >> 2) * 8 + (w >> 2)) << 4) + ((h & 3) << 2) + (w & 3);
        xh[(((size_t)(b * 1024 + tokloc)) << 9) + c0 + tx] = tile[tx][ty + r];
    }
}

// ---------------- K5: window-ordered [T,C] -> [B,C,H,W] --------------------
__global__ void permute_out_kernel(const float* __restrict__ xf, float* __restrict__ out) {
    __shared__ float tile[32][33];
    int b  = blockIdx.z;
    int hw0 = blockIdx.x * 32;
    int c0  = blockIdx.y * 32;
    int tx = threadIdx.x, ty = threadIdx.y;
    #pragma unroll
    for (int r = 0; r < 32; r += 8) {
        int hw = hw0 + ty + r;
        int h = hw >> 5, w = hw & 31;
        int tokloc = (((h >> 2) * 8 + (w >> 2)) << 4) + ((h & 3) << 2) + (w & 3);
        tile[ty + r][tx] = xf[(((size_t)(b * 1024 + tokloc)) << 9) + c0 + tx];
    }
    __syncthreads();
    #pragma unroll
    for (int r = 0; r < 32; r += 8) {
        int c = c0 + ty + r;
        out[(((size_t)(b * Cv + c)) << 10) + hw0 + tx] = tile[tx][ty + r];
    }
}

// ---------------- LayerNorm: warp per token (row of 512) -------------------
__global__ void ln_kernel(const float* __restrict__ src, const float* __restrict__ w,
                          const float* __restrict__ b, float* __restrict__ dst) {
    int warp = (blockIdx.x * blockDim.x + threadIdx.x) >> 5;
    int lane = threadIdx.x & 31;
    const float4* row = (const float4*)(src + ((size_t)warp << 9));
    float4 v[4];
    float s = 0.f, s2 = 0.f;
    #pragma unroll
    for (int r = 0; r < 4; r++) {
        v[r] = row[lane + (r << 5)];
        s  += v[r].x + v[r].y + v[r].z + v[r].w;
        s2 += v[r].x * v[r].x + v[r].y * v[r].y + v[r].z * v[r].z + v[r].w * v[r].w;
    }
    #pragma unroll
    for (int o = 16; o > 0; o >>= 1) {
        s  += __shfl_xor_sync(0xffffffffu, s,  o);
        s2 += __shfl_xor_sync(0xffffffffu, s2, o);
    }
    float mean = s * (1.f / 512.f);
    float var  = s2 * (1.f / 512.f) - mean * mean;
    float rstd = rsqrtf(var + EPSv);
    float4* drow = (float4*)(dst + ((size_t)warp << 9));
    const float4* wv4 = (const float4*)w;
    const float4* bv4 = (const float4*)b;
    #pragma unroll
    for (int r = 0; r < 4; r++) {
        float4 wv = wv4[lane + (r << 5)];
        float4 bv = bv4[lane + (r << 5)];
        float4 o;
        o.x = (v[r].x - mean) * rstd * wv.x + bv.x;
        o.y = (v[r].y - mean) * rstd * wv.y + bv.y;
        o.z = (v[r].z - mean) * rstd * wv.z + bv.z;
        o.w = (v[r].w - mean) * rstd * wv.w + bv.w;
        drow[lane + (r << 5)] = o;
    }
}

// ---------------- SGEMM: out[M,Nn] = A[M,K] @ W[Nn,K]^T + bias (+epi) ------
// EPI: 0 = bias, 1 = bias + exact gelu, 2 = bias + residual add
template <int EPI>
__global__ __launch_bounds__(256) void sgemm_kernel(
    const float* __restrict__ A, const float* __restrict__ Wm,
    const float* __restrict__ bias, const float* __restrict__ res,
    float* __restrict__ out, int M, int Nn, int K) {
    __shared__ float As[8][128];
    __shared__ float Bs[8][128];
    int tid = threadIdx.x;
    int bx = blockIdx.x;           // n tile
    int by = blockIdx.y;           // m tile
    int tx = tid & 15, ty = tid >> 4;
    int arow = tid >> 1;
    int ak   = (tid & 1) * 4;
    const float* Aptr = A  + ((size_t)(by * 128 + arow)) * K + ak;
    const float* Bptr = Wm + ((size_t)(bx * 128 + arow)) * K + ak;

    float acc[8][8];
    #pragma unroll
    for (int i = 0; i < 8; i++)
        #pragma unroll
        for (int j = 0; j < 8; j++) acc[i][j] = 0.f;

    for (int k0 = 0; k0 < K; k0 += 8) {
        float4 av = *(const float4*)(Aptr + k0);
        float4 bv = *(const float4*)(Bptr + k0);
        __syncthreads();
        As[ak + 0][arow] = av.x; As[ak + 1][arow] = av.y;
        As[ak + 2][arow] = av.z; As[ak + 3][arow] = av.w;
        Bs[ak + 0][arow] = bv.x; Bs[ak + 1][arow] = bv.y;
        Bs[ak + 2][arow] = bv.z; Bs[ak + 3][arow] = bv.w;
        __syncthreads();
        #pragma unroll
        for (int k = 0; k < 8; k++) {
            float a[8], b[8];
            const float4* a4 = (const float4*)&As[k][ty * 8];
            const float4* b4 = (const float4*)&Bs[k][tx * 8];
            float4 t0 = a4[0], t1 = a4[1];
            a[0]=t0.x; a[1]=t0.y; a[2]=t0.z; a[3]=t0.w;
            a[4]=t1.x; a[5]=t1.y; a[6]=t1.z; a[7]=t1.w;
            float4 u0 = b4[0], u1 = b4[1];
            b[0]=u0.x; b[1]=u0.y; b[2]=u0.z; b[3]=u0.w;
            b[4]=u1.x; b[5]=u1.y; b[6]=u1.z; b[7]=u1.w;
            #pragma unroll
            for (int i = 0; i < 8; i++)
                #pragma unroll
                for (int j = 0; j < 8; j++)
                    acc[i][j] += a[i] * b[j];
        }
    }

    int m0 = by * 128 + ty * 8;
    int n0 = bx * 128 + tx * 8;
    float bsv[8];
    #pragma unroll
    for (int j = 0; j < 8; j++) bsv[j] = bias[n0 + j];
    #pragma unroll
    for (int i = 0; i < 8; i++) {
        size_t rowoff = ((size_t)(m0 + i)) * Nn + n0;
        float v[8];
        #pragma unroll
        for (int j = 0; j < 8; j++) {
            float t = acc[i][j] + bsv[j];
            if (EPI == 1) t = 0.5f * t * (1.0f + erff(t * 0.7071067811865476f));
            v[j] = t;
        }
        if (EPI == 2) {
            const float4* r4 = (const float4*)(res + rowoff);
            float4 r0 = r4[0], r1 = r4[1];
            v[0]+=r0.x; v[1]+=r0.y; v[2]+=r0.z; v[3]+=r0.w;
            v[4]+=r1.x; v[5]+=r1.y; v[6]+=r1.z; v[7]+=r1.w;
        }
        float4* o4 = (float4*)(out + rowoff);
        o4[0] = make_float4(v[0], v[1], v[2], v[3]);
        o4[1] = make_float4(v[4], v[5], v[6], v[7]);
    }
}

// ---------------- Attention: warp per (window, head) -----------------------
__global__ __launch_bounds__(128) void attn_kernel(const float* __restrict__ qkv,
                                                   const float* __restrict__ rpb,
                                                   float* __restrict__ outp) {
    __shared__ float sq[4][16][33];
    __shared__ float sk[4][16][33];
    __shared__ float sv[4][16][33];
    __shared__ float sa[4][16][16];
    int wid  = threadIdx.x >> 5;
    int lane = threadIdx.x & 31;
    int win  = blockIdx.x;
    int h    = blockIdx.y * 4 + wid;
    int wbase = win * 16;

    // load q (scaled), k, v for this head
    for (int idx = lane; idx < 512; idx += 32) {
        int t = idx >> 5, d = idx & 31;
        size_t base = ((size_t)(wbase + t)) * C3v + h * HDv + d;
        sq[wid][t][d] = qkv[base] * QSCALE;
        sk[wid][t][d] = qkv[base + Cv];
        sv[wid][t][d] = qkv[base + 2 * Cv];
    }
    __syncwarp();

    // attn = q k^T + relative position bias
    for (int e = lane; e < 256; e += 32) {
        int n = e >> 4, m = e & 15;
        float s = 0.f;
        #pragma unroll
        for (int d = 0; d < 32; d++) s += sq[wid][n][d] * sk[wid][m][d];
        int ni = n >> 2, nj = n & 3, mi = m >> 2, mj = m & 3;
        int ridx = (ni - mi + 3) * 7 + (nj - mj + 3);
        s += rpb[ridx * NHv + h];
        sa[wid][n][m] = s;
    }
    __syncwarp();

    // softmax per row (2 lanes per row, 8 cols each)
    {
        int n  = lane >> 1;
        int m0 = (lane & 1) * 8;
        float mx = -1e30f;
        #pragma unroll
        for (int m = 0; m < 8; m++) mx = fmaxf(mx, sa[wid][n][m0 + m]);
        mx = fmaxf(mx, __shfl_xor_sync(0xffffffffu, mx, 1));
        float ev[8], sum = 0.f;
        #pragma unroll
        for (int m = 0; m < 8; m++) { ev[m] = __expf(sa[wid][n][m0 + m] - mx); sum += ev[m]; }
        sum += __shfl_xor_sync(0xffffffffu, sum, 1);
        float inv = 1.f / sum;
        #pragma unroll
        for (int m = 0; m < 8; m++) sa[wid][n][m0 + m] = ev[m] * inv;
    }
    __syncwarp();

    // out = attn @ v  -> [token, h*32 + d]
    for (int idx = lane; idx < 512; idx += 32) {
        int n = idx >> 5, d = idx & 31;
        float s = 0.f;
        #pragma unroll
        for (int m = 0; m < 16; m++) s += sa[wid][n][m] * sv[wid][m][d];
        outp[((size_t)(wbase + n)) * Cv + h * HDv + d] = s;
    }
}

// ---------------- launch ---------------------------------------------------
extern "C" void kernel_launch(void* const* d_in, const int* in_sizes, int n_in,
                              void* d_out, int out_size) {
    const float* x     = (const float*)d_in[0];
    const float* n1w   = (const float*)d_in[1];
    const float* n1b   = (const float*)d_in[2];
    const float* qkvw  = (const float*)d_in[3];
    const float* qkvb  = (const float*)d_in[4];
    const float* rpb   = (const float*)d_in[5];
    const float* projw = (const float*)d_in[6];
    const float* projb = (const float*)d_in[7];
    const float* n2w   = (const float*)d_in[8];
    const float* n2b   = (const float*)d_in[9];
    const float* w1    = (const float*)d_in[10];
    const float* b1    = (const float*)d_in[11];
    const float* w2    = (const float*)d_in[12];
    const float* b2    = (const float*)d_in[13];
    float* out = (float*)d_out;

    float *p_xh, *p_xn, *p_qkv, *p_att, *p_xh2, *p_h2, *p_hid, *p_xfin;
    cudaGetSymbolAddress((void**)&p_xh,   g_xh);
    cudaGetSymbolAddress((void**)&p_xn,   g_xn);
    cudaGetSymbolAddress((void**)&p_qkv,  g_qkv);
    cudaGetSymbolAddress((void**)&p_att,  g_att);
    cudaGetSymbolAddress((void**)&p_xh2,  g_xh2);
    cudaGetSymbolAddress((void**)&p_h2,   g_h2);
    cudaGetSymbolAddress((void**)&p_hid,  g_hid);
    cudaGetSymbolAddress((void**)&p_xfin, g_xfin);

    dim3 tb(32, 8);
    dim3 tg(32, 16, 32);  // hw tiles, c tiles, batch

    // 1) permute to window order
    permute_in_kernel<<<tg, tb>>>(x, p_xh);
    // 2) LN1
    ln_kernel<<<Tv * 32 / 256, 256>>>(p_xh, n1w, n1b, p_xn);
    // 3) qkv = xn @ qkv_w^T + b
    sgemm_kernel<0><<<dim3(C3v / 128, Tv / 128), 256>>>(p_xn, qkvw, qkvb, nullptr, p_qkv, Tv, C3v, Cv);
    // 4) window attention
    attn_kernel<<<dim3(2048, 4), 128>>>(p_qkv, rpb, p_att);
    // 5) proj + residual(xh)
    sgemm_kernel<2><<<dim3(Cv / 128, Tv / 128), 256>>>(p_att, projw, projb, p_xh, p_xh2, Tv, Cv, Cv);
    // 6) LN2
    ln_kernel<<<Tv * 32 / 256, 256>>>(p_xh2, n2w, n2b, p_h2);
    // 7) mlp1 + gelu
    sgemm_kernel<1><<<dim3(MLPHv / 128, Tv / 128), 256>>>(p_h2, w1, b1, nullptr, p_hid, Tv, MLPHv, Cv);
    // 8) mlp2 + residual(xh2)
    sgemm_kernel<2><<<dim3(Cv / 128, Tv / 128), 256>>>(p_hid, w2, b2, p_xh2, p_xfin, Tv, Cv, MLPHv);
    // 9) permute back to [B,C,H,W]
    permute_out_kernel<<<tg, tb>>>(p_xfin, out);
}

// round 2
// speedup vs baseline: 2.4836x; 2.4836x over previous
#include <cuda_runtime.h>
#include <cuda_bf16.h>
#include <math.h>

// Problem constants
#define Bv 32
#define Cv 512
#define Hv 32
#define Wv 32
#define NHv 16
#define WSv 4
#define HDv 32
#define Nv 16
#define Tv 32768              // B*H*W tokens
#define C3v 1536
#define MLPHv 2048
#define EPSv 1e-5f
#define QSCALE 0.1767766952966369f  // 1/sqrt(32)

// ---------------- scratch (device globals; no allocation allowed) ----------
__device__ float g_xh  [Tv * Cv];     // permuted input (window order), residual 1
__device__ float g_xn  [Tv * Cv];     // LN1 output
__device__ float g_qkv [Tv * C3v];    // qkv projection
__device__ float g_att [Tv * Cv];     // attention output (pre-proj)
__device__ float g_xh2 [Tv * Cv];     // after proj + residual
__device__ float g_h2  [Tv * Cv];     // LN2 output
__device__ float g_hid [Tv * MLPHv];  // mlp hidden
__device__ float g_xfin[Tv * Cv];     // final (window order)

// ---------------- helpers --------------------------------------------------
__device__ __forceinline__ unsigned smem_u32(const void* p) {
    return (unsigned)__cvta_generic_to_shared(p);
}
__device__ __forceinline__ unsigned f2tf(float f) {
    unsigned r;
    asm("cvt.rna.tf32.f32 %0, %1;" : "=r"(r) : "f"(f));
    return r;
}
#define CP_ASYNC16(dst, src) \
    asm volatile("cp.async.ca.shared.global [%0], [%1], 16;" :: "r"(dst), "l"(src))
#define CP_COMMIT() asm volatile("cp.async.commit_group;")
#define CP_WAIT0()  asm volatile("cp.async.wait_group 0;")
#define CP_WAIT1()  asm volatile("cp.async.wait_group 1;")

#define MMA_TF32(d, a, b) \
    asm volatile("mma.sync.aligned.m16n8k8.row.col.f32.tf32.tf32.f32 " \
        "{%0,%1,%2,%3}, {%4,%5,%6,%7}, {%8,%9}, {%0,%1,%2,%3};" \
        : "+f"(d[0]), "+f"(d[1]), "+f"(d[2]), "+f"(d[3]) \
        : "r"(a[0]), "r"(a[1]), "r"(a[2]), "r"(a[3]), "r"(b[0]), "r"(b[1]))

// ---------------- K1a: [B,C,H,W] -> window-ordered [T,C] -------------------
__global__ void permute_in_kernel(const float* __restrict__ x, float* __restrict__ xh) {
    __shared__ float tile[32][33];
    int b  = blockIdx.z;
    int hw0 = blockIdx.x * 32;
    int c0  = blockIdx.y * 32;
    int tx = threadIdx.x, ty = threadIdx.y;
    #pragma unroll
    for (int r = 0; r < 32; r += 8) {
        int c = c0 + ty + r;
        tile[ty + r][tx] = x[(((size_t)(b * Cv + c)) << 10) + hw0 + tx];
    }
    __syncthreads();
    #pragma unroll
    for (int r = 0; r < 32; r += 8) {
        int hw = hw0 + ty + r;
        int h = hw >> 5, w = hw & 31;
        int tokloc = (((h >> 2) * 8 + (w >> 2)) << 4) + ((h & 3) << 2) + (w & 3);
        xh[(((size_t)(b * 1024 + tokloc)) << 9) + c0 + tx] = tile[tx][ty + r];
    }
}

// ---------------- window-ordered [T,C] -> [B,C,H,W] ------------------------
__global__ void permute_out_kernel(const float* __restrict__ xf, float* __restrict__ out) {
    __shared__ float tile[32][33];
    int b  = blockIdx.z;
    int hw0 = blockIdx.x * 32;
    int c0  = blockIdx.y * 32;
    int tx = threadIdx.x, ty = threadIdx.y;
    #pragma unroll
    for (int r = 0; r < 32; r += 8) {
        int hw = hw0 + ty + r;
        int h = hw >> 5, w = hw & 31;
        int tokloc = (((h >> 2) * 8 + (w >> 2)) << 4) + ((h & 3) << 2) + (w & 3);
        tile[ty + r][tx] = xf[(((size_t)(b * 1024 + tokloc)) << 9) + c0 + tx];
    }
    __syncthreads();
    #pragma unroll
    for (int r = 0; r < 32; r += 8) {
        int c = c0 + ty + r;
        out[(((size_t)(b * Cv + c)) << 10) + hw0 + tx] = tile[tx][ty + r];
    }
}

// ---------------- LayerNorm: warp per token (row of 512) -------------------
__global__ void ln_kernel(const float* __restrict__ src, const float* __restrict__ w,
                          const float* __restrict__ b, float* __restrict__ dst) {
    int warp = (blockIdx.x * blockDim.x + threadIdx.x) >> 5;
    int lane = threadIdx.x & 31;
    const float4* row = (const float4*)(src + ((size_t)warp << 9));
    float4 v[4];
    float s = 0.f, s2 = 0.f;
    #pragma unroll
    for (int r = 0; r < 4; r++) {
        v[r] = row[lane + (r << 5)];
        s  += v[r].x + v[r].y + v[r].z + v[r].w;
        s2 += v[r].x * v[r].x + v[r].y * v[r].y + v[r].z * v[r].z + v[r].w * v[r].w;
    }
    #pragma unroll
    for (int o = 16; o > 0; o >>= 1) {
        s  += __shfl_xor_sync(0xffffffffu, s,  o);
        s2 += __shfl_xor_sync(0xffffffffu, s2, o);
    }
    float mean = s * (1.f / 512.f);
    float var  = s2 * (1.f / 512.f) - mean * mean;
    float rstd = rsqrtf(var + EPSv);
    float4* drow = (float4*)(dst + ((size_t)warp << 9));
    const float4* wv4 = (const float4*)w;
    const float4* bv4 = (const float4*)b;
    #pragma unroll
    for (int r = 0; r < 4; r++) {
        float4 wv = wv4[lane + (r << 5)];
        float4 bv = bv4[lane + (r << 5)];
        float4 o;
        o.x = (v[r].x - mean) * rstd * wv.x + bv.x;
        o.y = (v[r].y - mean) * rstd * wv.y + bv.y;
        o.z = (v[r].z - mean) * rstd * wv.z + bv.z;
        o.w = (v[r].w - mean) * rstd * wv.w + bv.w;
        drow[lane + (r << 5)] = o;
    }
}

// ---------------- TF32 tensor-core GEMM ------------------------------------
// out[M,Nn] = A[M,K] @ W[Nn,K]^T + bias, with epilogue:
// EPI: 0 = bias, 1 = bias + exact gelu, 2 = bias + residual add
// 128x128 tile, BK=16, 8 warps each 64x32, cp.async double-buffered.
#define LDA_S 20   // smem row stride (floats); conflict-free for frag pattern

template <int EPI>
__global__ __launch_bounds__(256) void tgemm_kernel(
    const float* __restrict__ A, const float* __restrict__ Wm,
    const float* __restrict__ bias, const float* __restrict__ res,
    float* __restrict__ out, int M, int Nn, int K) {
    __shared__ float As[2][128 * LDA_S];
    __shared__ float Ws[2][128 * LDA_S];

    int tid  = threadIdx.x;
    int warp = tid >> 5, lane = tid & 31;
    int gid  = lane >> 2, tig = lane & 3;
    int wm = (warp & 1) * 64;      // warp m offset within tile
    int wn = (warp >> 1) * 32;     // warp n offset within tile
    int m0 = blockIdx.y * 128;
    int n0 = blockIdx.x * 128;

    // loader mapping: each thread moves 2 rows x 1 float4 per matrix
    int lr = tid >> 2;             // 0..63
    int lc = (tid & 3) * 4;        // 0,4,8,12
    const float* Ag0 = A  + ((size_t)(m0 + lr)      ) * K + lc;
    const float* Ag1 = A  + ((size_t)(m0 + lr + 64) ) * K + lc;
    const float* Wg0 = Wm + ((size_t)(n0 + lr)      ) * K + lc;
    const float* Wg1 = Wm + ((size_t)(n0 + lr + 64) ) * K + lc;
    unsigned sA0[2], sA1[2], sW0[2], sW1[2];
    #pragma unroll
    for (int s = 0; s < 2; s++) {
        sA0[s] = smem_u32(&As[s][lr * LDA_S + lc]);
        sA1[s] = smem_u32(&As[s][(lr + 64) * LDA_S + lc]);
        sW0[s] = smem_u32(&Ws[s][lr * LDA_S + lc]);
        sW1[s] = smem_u32(&Ws[s][(lr + 64) * LDA_S + lc]);
    }

    float acc[4][4][4];
    #pragma unroll
    for (int mi = 0; mi < 4; mi++)
        #pragma unroll
        for (int ni = 0; ni < 4; ni++)
            #pragma unroll
            for (int r = 0; r < 4; r++) acc[mi][ni][r] = 0.f;

    int nIter = K >> 4;

    // prologue: stage 0
    CP_ASYNC16(sA0[0], Ag0); CP_ASYNC16(sA1[0], Ag1);
    CP_ASYNC16(sW0[0], Wg0); CP_ASYNC16(sW1[0], Wg1);
    CP_COMMIT();

    for (int it = 0; it < nIter; it++) {
        if (it + 1 < nIter) {
            int nb = (it + 1) & 1;
            int ko = (it + 1) << 4;
            CP_ASYNC16(sA0[nb], Ag0 + ko); CP_ASYNC16(sA1[nb], Ag1 + ko);
            CP_ASYNC16(sW0[nb], Wg0 + ko); CP_ASYNC16(sW1[nb], Wg1 + ko);
            CP_COMMIT();
            CP_WAIT1();
        } else {
            CP_WAIT0();
        }
        __syncthreads();

        const float* Ac = As[it & 1];
        const float* Wc = Ws[it & 1];
        #pragma unroll
        for (int ks = 0; ks < 2; ks++) {
            int kk = ks * 8;
            unsigned af[4][4], bf[4][2];
            #pragma unroll
            for (int mi = 0; mi < 4; mi++) {
                int r = wm + mi * 16 + gid;
                af[mi][0] = f2tf(Ac[ r      * LDA_S + kk + tig]);
                af[mi][1] = f2tf(Ac[(r + 8) * LDA_S + kk + tig]);
                af[mi][2] = f2tf(Ac[ r      * LDA_S + kk + tig + 4]);
                af[mi][3] = f2tf(Ac[(r + 8) * LDA_S + kk + tig + 4]);
            }
            #pragma unroll
            for (int ni = 0; ni < 4; ni++) {
                int r = wn + ni * 8 + gid;
                bf[ni][0] = f2tf(Wc[r * LDA_S + kk + tig]);
                bf[ni][1] = f2tf(Wc[r * LDA_S + kk + tig + 4]);
            }
            #pragma unroll
            for (int mi = 0; mi < 4; mi++)
                #pragma unroll
                for (int ni = 0; ni < 4; ni++)
                    MMA_TF32(acc[mi][ni], af[mi], bf[ni]);
        }
        __syncthreads();
    }

    // epilogue
    #pragma unroll
    for (int ni = 0; ni < 4; ni++) {
        int col = n0 + wn + ni * 8 + tig * 2;
        float b0 = bias[col], b1 = bias[col + 1];
        #pragma unroll
        for (int mi = 0; mi < 4; mi++) {
            #pragma unroll
            for (int rr = 0; rr < 2; rr++) {
                int row = m0 + wm + mi * 16 + gid + rr * 8;
                float v0 = acc[mi][ni][rr * 2 + 0] + b0;
                float v1 = acc[mi][ni][rr * 2 + 1] + b1;
                if (EPI == 1) {
                    v0 = 0.5f * v0 * (1.0f + erff(v0 * 0.7071067811865476f));
                    v1 = 0.5f * v1 * (1.0f + erff(v1 * 0.7071067811865476f));
                }
                size_t off = (size_t)row * Nn + col;
                if (EPI == 2) {
                    float2 rv = *(const float2*)(res + off);
                    v0 += rv.x; v1 += rv.y;
                }
                *(float2*)(out + off) = make_float2(v0, v1);
            }
        }
    }
}

// ---------------- Attention: warp per (window, head) -----------------------
__global__ __launch_bounds__(128) void attn_kernel(const float* __restrict__ qkv,
                                                   const float* __restrict__ rpb,
                                                   float* __restrict__ outp) {
    __shared__ float sq[4][16][33];
    __shared__ float sk[4][16][33];
    __shared__ float sv[4][16][33];
    __shared__ float sa[4][16][16];
    int wid  = threadIdx.x >> 5;
    int lane = threadIdx.x & 31;
    int win  = blockIdx.x;
    int h    = blockIdx.y * 4 + wid;
    int wbase = win * 16;

    for (int idx = lane; idx < 512; idx += 32) {
        int t = idx >> 5, d = idx & 31;
        size_t base = ((size_t)(wbase + t)) * C3v + h * HDv + d;
        sq[wid][t][d] = qkv[base] * QSCALE;
        sk[wid][t][d] = qkv[base + Cv];
        sv[wid][t][d] = qkv[base + 2 * Cv];
    }
    __syncwarp();

    for (int e = lane; e < 256; e += 32) {
        int n = e >> 4, m = e & 15;
        float s = 0.f;
        #pragma unroll
        for (int d = 0; d < 32; d++) s += sq[wid][n][d] * sk[wid][m][d];
        int ni = n >> 2, nj = n & 3, mi = m >> 2, mj = m & 3;
        int ridx = (ni - mi + 3) * 7 + (nj - mj + 3);
        s += rpb[ridx * NHv + h];
        sa[wid][n][m] = s;
    }
    __syncwarp();

    {
        int n  = lane >> 1;
        int m0 = (lane & 1) * 8;
        float mx = -1e30f;
        #pragma unroll
        for (int m = 0; m < 8; m++) mx = fmaxf(mx, sa[wid][n][m0 + m]);
        mx = fmaxf(mx, __shfl_xor_sync(0xffffffffu, mx, 1));
        float ev[8], sum = 0.f;
        #pragma unroll
        for (int m = 0; m < 8; m++) { ev[m] = __expf(sa[wid][n][m0 + m] - mx); sum += ev[m]; }
        sum += __shfl_xor_sync(0xffffffffu, sum, 1);
        float inv = 1.f / sum;
        #pragma unroll
        for (int m = 0; m < 8; m++) sa[wid][n][m0 + m] = ev[m] * inv;
    }
    __syncwarp();

    for (int idx = lane; idx < 512; idx += 32) {
        int n = idx >> 5, d = idx & 31;
        float s = 0.f;
        #pragma unroll
        for (int m = 0; m < 16; m++) s += sa[wid][n][m] * sv[wid][m][d];
        outp[((size_t)(wbase + n)) * Cv + h * HDv + d] = s;
    }
}

// ---------------- launch ---------------------------------------------------
extern "C" void kernel_launch(void* const* d_in, const int* in_sizes, int n_in,
                              void* d_out, int out_size) {
    const float* x     = (const float*)d_in[0];
    const float* n1w   = (const float*)d_in[1];
    const float* n1b   = (const float*)d_in[2];
    const float* qkvw  = (const float*)d_in[3];
    const float* qkvb  = (const float*)d_in[4];
    const float* rpb   = (const float*)d_in[5];
    const float* projw = (const float*)d_in[6];
    const float* projb = (const float*)d_in[7];
    const float* n2w   = (const float*)d_in[8];
    const float* n2b   = (const float*)d_in[9];
    const float* w1    = (const float*)d_in[10];
    const float* b1    = (const float*)d_in[11];
    const float* w2    = (const float*)d_in[12];
    const float* b2    = (const float*)d_in[13];
    float* out = (float*)d_out;

    float *p_xh, *p_xn, *p_qkv, *p_att, *p_xh2, *p_h2, *p_hid, *p_xfin;
    cudaGetSymbolAddress((void**)&p_xh,   g_xh);
    cudaGetSymbolAddress((void**)&p_xn,   g_xn);
    cudaGetSymbolAddress((void**)&p_qkv,  g_qkv);
    cudaGetSymbolAddress((void**)&p_att,  g_att);
    cudaGetSymbolAddress((void**)&p_xh2,  g_xh2);
    cudaGetSymbolAddress((void**)&p_h2,   g_h2);
    cudaGetSymbolAddress((void**)&p_hid,  g_hid);
    cudaGetSymbolAddress((void**)&p_xfin, g_xfin);

    dim3 tb(32, 8);
    dim3 tg(32, 16, 32);  // hw tiles, c tiles, batch

    // 1) permute to window order
    permute_in_kernel<<<tg, tb>>>(x, p_xh);
    // 2) LN1
    ln_kernel<<<Tv * 32 / 256, 256>>>(p_xh, n1w, n1b, p_xn);
    // 3) qkv = xn @ qkv_w^T + b   [32768,1536] = [32768,512]x[1536,512]^T
    tgemm_kernel<0><<<dim3(C3v / 128, Tv / 128), 256>>>(p_xn, qkvw, qkvb, nullptr, p_qkv, Tv, C3v, Cv);
    // 4) window attention
    attn_kernel<<<dim3(2048, 4), 128>>>(p_qkv, rpb, p_att);
    // 5) proj + residual(xh)
    tgemm_kernel<2><<<dim3(Cv / 128, Tv / 128), 256>>>(p_att, projw, projb, p_xh, p_xh2, Tv, Cv, Cv);
    // 6) LN2
    ln_kernel<<<Tv * 32 / 256, 256>>>(p_xh2, n2w, n2b, p_h2);
    // 7) mlp1 + gelu
    tgemm_kernel<1><<<dim3(MLPHv / 128, Tv / 128), 256>>>(p_h2, w1, b1, nullptr, p_hid, Tv, MLPHv, Cv);
    // 8) mlp2 + residual(xh2)
    tgemm_kernel<2><<<dim3(Cv / 128, Tv / 128), 256>>>(p_hid, w2, b2, p_xh2, p_xfin, Tv, Cv, MLPHv);
    // 9) permute back to [B,C,H,W]
    permute_out_kernel<<<tg, tb>>>(p_xfin, out);
}